// round 4
// baseline (speedup 1.0000x reference)
#include <cuda_runtime.h>

// QuantumConv closed form (R1 derivation):
//   p1 = 0.5 * ( 1 - cos(pi*t0)*cos(pi*t1)*cos(f0)
//                  + sin(pi*t0)*cos(pi*t1)*sin(f0)*cos(f1)*cos(f8) )
// with f0 = in[b,y,x], f1 = in[b,y,x+1], f8 = in[b,y+2,x+2].
//
// R4 change: 4 outputs per thread with a single float4 store.
// NP = 10816 = 4*2704, so every 4-group is whole and 16B-aligned in out.
// Thread count 10816 -> 2704 (22 blocks), theta trig + launch work amortized.

#define BATCH 16
#define HH 28
#define WW 28
#define NOUT 26
#define NP (BATCH * NOUT * NOUT)   // 10816
#define NP4 (NP / 4)               // 2704 threads

__global__ __launch_bounds__(128, 1)
void qconv_closed_form_v4(const float* __restrict__ in,
                          const float* __restrict__ theta,
                          float* __restrict__ out) {
    int g = blockIdx.x * blockDim.x + threadIdx.x;   // group id
    if (g >= NP4) return;
    int idx0 = g * 4;

    // Uniform theta factors (same for all threads; MUFU, cheap).
    const float PI = 3.14159265358979323846f;
    float sa, ca;
    __sincosf(PI * __ldg(theta), &sa, &ca);
    float cb = __cosf(PI * __ldg(theta + 1));
    float K1 = ca * cb;          // cos(pi t0) cos(pi t1)
    float K2 = sa * cb;          // sin(pi t0) cos(pi t1)

    float f0[4], f1[4], f8[4];
    #pragma unroll
    for (int e = 0; e < 4; e++) {
        int idx = idx0 + e;
        int t = idx / NOUT;
        int x = idx - t * NOUT;
        int b = t / NOUT;
        int y = t - b * NOUT;
        const float* base = in + (b * HH + y) * WW + x;
        f0[e] = __ldg(base);
        f1[e] = __ldg(base + 1);
        f8[e] = __ldg(base + 2 * WW + 2);
    }

    float4 r;
    float* rp = &r.x;
    #pragma unroll
    for (int e = 0; e < 4; e++) {
        float s0, c0;
        __sincosf(f0[e], &s0, &c0);
        rp[e] = 0.5f * (1.0f - K1 * c0 + K2 * s0 * __cosf(f1[e]) * __cosf(f8[e]));
    }

    *reinterpret_cast<float4*>(out + idx0) = r;
}

extern "C" void kernel_launch(void* const* d_in, const int* in_sizes, int n_in,
                              void* d_out, int out_size) {
    const float* input = (const float*)d_in[0];   // (16,28,28) float32
    const float* theta = (const float*)d_in[1];   // (1,27) float32
    float* out = (float*)d_out;                   // (16,26,26) float32

    (void)in_sizes; (void)n_in; (void)out_size;

    int threads = 128;
    int blocks = (NP4 + threads - 1) / threads;   // 22 blocks
    qconv_closed_form_v4<<<blocks, threads>>>(input, theta, out);
}

// round 6
// speedup vs baseline: 1.3542x; 1.3542x over previous
#include <cuda_runtime.h>

// QuantumConv closed form (R1 derivation):
//   p1 = 0.5 - 0.5*cos(pi*t0)*cos(pi*t1)*cos(f0)
//            + 0.5*sin(pi*t0)*cos(pi*t1)*sin(f0)*cos(f1)*cos(f8)
// with f0 = in[b,y,x], f1 = in[b,y,x+1], f8 = in[b,y+2,x+2].
//
// R5: revert to R3 shape (1 output/thread — max TLP; R4 showed ILP-4 regresses
// this latency-bound kernel) + FMA-folded epilogue with pre-halved constants.

#define BATCH 16
#define HH 28
#define WW 28
#define NOUT 26
#define NP (BATCH * NOUT * NOUT)   // 10816

__global__ __launch_bounds__(128, 1)
void qconv_closed_form(const float* __restrict__ in,
                       const float* __restrict__ theta,
                       float* __restrict__ out) {
    int idx = blockIdx.x * blockDim.x + threadIdx.x;
    if (idx >= NP) return;

    int t = idx / NOUT;          // const-div -> mulhi
    int x = idx - t * NOUT;
    int b = t / NOUT;
    int y = t - b * NOUT;

    const float* base = in + (b * HH + y) * WW + x;

    // Batch all 5 loads before any dependent math (MLP=5, L2-warm on replay).
    float f0 = __ldg(base);
    float f1 = __ldg(base + 1);
    float f8 = __ldg(base + 2 * WW + 2);
    float t0 = __ldg(theta);
    float t1 = __ldg(theta + 1);

    const float PI = 3.14159265358979323846f;

    // Theta MUFUs — independent of the data MUFUs below, overlap freely.
    float sa, ca;
    __sincosf(PI * t0, &sa, &ca);
    float cbh = 0.5f * __cosf(PI * t1);
    float K1h = ca * cbh;        // 0.5 * cos(pi t0) cos(pi t1)
    float K2h = sa * cbh;        // 0.5 * sin(pi t0) cos(pi t1)

    float s0, c0;
    __sincosf(f0, &s0, &c0);
    float c18 = __cosf(f1) * __cosf(f8);

    out[idx] = fmaf(K2h, s0 * c18, fmaf(-K1h, c0, 0.5f));
}

extern "C" void kernel_launch(void* const* d_in, const int* in_sizes, int n_in,
                              void* d_out, int out_size) {
    const float* input = (const float*)d_in[0];   // (16,28,28) float32
    const float* theta = (const float*)d_in[1];   // (1,27) float32
    float* out = (float*)d_out;                   // (16,26,26) float32

    (void)in_sizes; (void)n_in; (void)out_size;

    int threads = 128;
    int blocks = (NP + threads - 1) / threads;    // 85 blocks, single wave
    qconv_closed_form<<<blocks, threads>>>(input, theta, out);
}